// round 1
// baseline (speedup 1.0000x reference)
#include <cuda_runtime.h>
#include <math.h>

// Problem constants
#define H   512
#define CE  128
#define WE  256
#define U_  2048
#define TC  16
#define B_  256
#define TW  64
#define WD  (2*H + WE)   // 1280 word-input dim

// ---------------- scratch (device globals; allocation-free) ----------------
__device__ float g_char_x[(size_t)U_ * TC * CE];        // [U*TC, 128]
__device__ float g_Xg_c[(size_t)U_ * TC * 2 * H];       // [U*TC, 1024] x-proj gates (+bias)
__device__ float g_Xc_c[(size_t)U_ * TC * H];           // [U*TC, 512]  x-proj cand  (+bias)
__device__ float g_Hc [(size_t)2 * U_ * H];             // [4096, 512] fw rows 0..U-1, bw rows U..2U-1
__device__ float g_RHc[(size_t)2 * U_ * H];
__device__ float g_Uc [(size_t)2 * U_ * H];
__device__ float g_word_x[(size_t)B_ * TW * WD];        // [16384, 1280]
__device__ float g_Xg_w[(size_t)B_ * TW * 2 * H];
__device__ float g_Xc_w[(size_t)B_ * TW * H];
__device__ float g_Hw [(size_t)2 * B_ * H];
__device__ float g_RHw[(size_t)2 * B_ * H];
__device__ float g_Uw [(size_t)2 * B_ * H];
__device__ float g_states[(size_t)B_ * 2 * H];
__device__ float g_hidden[(size_t)B_ * 64];

// ---------------- 64x64 fp32 GEMM tile core (256 threads, 4x4/thread) ------
// C_tile(64x64) at (bm,bn) of A[M,K] @ B[K,N], row-major. K % 16 == 0.
__device__ __forceinline__ void gemm64(const float* __restrict__ A,
                                       const float* __restrict__ Bm,
                                       int K, int N, int bm, int bn,
                                       float acc[4][4]) {
    __shared__ float As[64][16];
    __shared__ float Bs[16][64];
    const int tid = threadIdx.x;
    const int tx = tid & 15;
    const int ty = tid >> 4;
    for (int k0 = 0; k0 < K; k0 += 16) {
        #pragma unroll
        for (int i = 0; i < 4; i++) {
            int idx = tid + i * 256;             // 0..1023
            int ra = idx >> 4, ca = idx & 15;    // A tile 64x16
            As[ra][ca] = A[(size_t)(bm + ra) * K + k0 + ca];
            int rb = idx >> 6, cb = idx & 63;    // B tile 16x64
            Bs[rb][cb] = Bm[(size_t)(k0 + rb) * N + bn + cb];
        }
        __syncthreads();
        #pragma unroll
        for (int k = 0; k < 16; k++) {
            float a[4], b[4];
            #pragma unroll
            for (int i = 0; i < 4; i++) a[i] = As[ty + 16 * i][k];
            #pragma unroll
            for (int j = 0; j < 4; j++) b[j] = Bs[k][tx + 16 * j];
            #pragma unroll
            for (int i = 0; i < 4; i++)
                #pragma unroll
                for (int j = 0; j < 4; j++)
                    acc[i][j] = fmaf(a[i], b[j], acc[i][j]);
        }
        __syncthreads();
    }
}

// ---------------- generic GEMM + bias (+optional leaky relu) ---------------
__global__ __launch_bounds__(256)
void k_sgemm_bias(const float* __restrict__ A, const float* __restrict__ Bm,
                  const float* __restrict__ bias, float* __restrict__ C,
                  int M, int N, int K, int act) {
    float acc[4][4] = {};
    int bm = blockIdx.y * 64, bn = blockIdx.x * 64;
    gemm64(A, Bm, K, N, bm, bn, acc);
    const int tx = threadIdx.x & 15, ty = threadIdx.x >> 4;
    #pragma unroll
    for (int i = 0; i < 4; i++) {
        int r = bm + ty + 16 * i;
        #pragma unroll
        for (int j = 0; j < 4; j++) {
            int c = bn + tx + 16 * j;
            float v = acc[i][j] + bias[c];
            if (act) v = v > 0.f ? v : 0.2f * v;
            C[(size_t)r * N + c] = v;
        }
    }
}

// ---------------- GRU step kernel 1: gates = sigmoid(Xg[t] + H @ Wgh) ------
// rows: [0,Nseq) = forward, [Nseq,2*Nseq) = backward. Writes r*h and u.
__global__ __launch_bounds__(256)
void k_gru_gates(const float* __restrict__ Hst, const float* __restrict__ Wgh,
                 const float* __restrict__ Xg, const int* __restrict__ lens,
                 float* __restrict__ RH, float* __restrict__ Ug,
                 int Nseq, int T, int t) {
    float acc[4][4] = {};
    int bm = blockIdx.y * 64, bn = blockIdx.x * 64;
    gemm64(Hst, Wgh, H, 2 * H, bm, bn, acc);
    const int tx = threadIdx.x & 15, ty = threadIdx.x >> 4;
    #pragma unroll
    for (int i = 0; i < 4; i++) {
        int r = bm + ty + 16 * i;
        int dir = (r >= Nseq);
        int n = dir ? r - Nseq : r;
        int len = lens[n];
        int te = dir ? max(0, min(len - 1 - t, T - 1)) : t;
        const float* xg = Xg + ((size_t)n * T + te) * (2 * H);
        #pragma unroll
        for (int j = 0; j < 4; j++) {
            int c = bn + tx + 16 * j;
            float g = 1.f / (1.f + expf(-(xg[c] + acc[i][j])));
            if (c < H) RH[(size_t)r * H + c] = g * Hst[(size_t)r * H + c];
            else       Ug[(size_t)r * H + (c - H)] = g;
        }
    }
}

// ---------------- GRU step kernel 2: c = tanh(Xc[t] + (r*h) @ Wch); update -
__global__ __launch_bounds__(256)
void k_gru_cand(float* __restrict__ Hst, const float* __restrict__ Wch,
                const float* __restrict__ Xc, const int* __restrict__ lens,
                const float* __restrict__ RH, const float* __restrict__ Ug,
                int Nseq, int T, int t) {
    float acc[4][4] = {};
    int bm = blockIdx.y * 64, bn = blockIdx.x * 64;
    gemm64(RH, Wch, H, H, bm, bn, acc);
    const int tx = threadIdx.x & 15, ty = threadIdx.x >> 4;
    #pragma unroll
    for (int i = 0; i < 4; i++) {
        int r = bm + ty + 16 * i;
        int dir = (r >= Nseq);
        int n = dir ? r - Nseq : r;
        int len = lens[n];
        if (t >= len) continue;  // h frozen past sequence end
        int te = dir ? max(0, min(len - 1 - t, T - 1)) : t;
        const float* xc = Xc + ((size_t)n * T + te) * H;
        #pragma unroll
        for (int j = 0; j < 4; j++) {
            int c = bn + tx + 16 * j;
            float cc = tanhf(xc[c] + acc[i][j]);
            float h = Hst[(size_t)r * H + c];
            float u = Ug[(size_t)r * H + c];
            Hst[(size_t)r * H + c] = u * h + (1.f - u) * cc;
        }
    }
}

// ---------------- gathers / small kernels -----------------------------------
__global__ void k_gather_char(const int* __restrict__ charseqs,
                              const float* __restrict__ char_emb,
                              float* __restrict__ out, int total) {
    int i = blockIdx.x * blockDim.x + threadIdx.x;
    if (i >= total) return;
    int c = i & (CE - 1);
    int w = i >> 7;                 // CE = 128
    int ch = charseqs[w];
    out[i] = char_emb[(size_t)ch * CE + c];
}

__global__ void k_gather_word(const int* __restrict__ cids,
                              const int* __restrict__ wids,
                              const float* __restrict__ word_emb,
                              const float* __restrict__ Hc,
                              float* __restrict__ out) {
    int i = blockIdx.x * blockDim.x + threadIdx.x;
    const int total = B_ * TW * WD;
    if (i >= total) return;
    int c = i % WD;
    int bt = i / WD;
    float v;
    if (c < H) {
        int id = cids[bt];
        v = Hc[(size_t)id * H + c];
    } else if (c < 2 * H) {
        int id = cids[bt];
        v = Hc[(size_t)(U_ + id) * H + (c - H)];
    } else {
        int w = wids[bt];
        v = word_emb[(size_t)w * WE + (c - 2 * H)];
    }
    out[i] = v;
}

__global__ void k_copy_states(const float* __restrict__ Hw, float* __restrict__ out) {
    int i = blockIdx.x * blockDim.x + threadIdx.x;
    if (i >= B_ * 2 * H) return;
    int c = i % (2 * H);
    int b = i / (2 * H);
    out[i] = (c < H) ? Hw[(size_t)b * H + c] : Hw[(size_t)(B_ + b) * H + (c - H)];
}

__global__ void k_fc2(const float* __restrict__ hidden, const float* __restrict__ W2,
                      const float* __restrict__ b2, float* __restrict__ out) {
    int i = blockIdx.x * blockDim.x + threadIdx.x;
    if (i >= B_ * 2) return;
    int b = i >> 1, j = i & 1;
    float s = b2[j];
    #pragma unroll
    for (int k = 0; k < 64; k++) s = fmaf(hidden[b * 64 + k], W2[k * 2 + j], s);
    out[i] = s;
}

// ---------------- host orchestration ----------------------------------------
extern "C" void kernel_launch(void* const* d_in, const int* in_sizes, int n_in,
                              void* d_out, int out_size) {
    const int*   charseqs      = (const int*)d_in[0];
    const int*   charseq_lens  = (const int*)d_in[1];
    const int*   charseq_ids   = (const int*)d_in[2];
    const int*   word_ids      = (const int*)d_in[3];
    const int*   sentence_lens = (const int*)d_in[4];
    const float* char_emb      = (const float*)d_in[5];
    const float* word_emb      = (const float*)d_in[6];
    const float* Wg_c = (const float*)d_in[7];
    const float* bg_c = (const float*)d_in[8];
    const float* Wc_c = (const float*)d_in[9];
    const float* bc_c = (const float*)d_in[10];
    const float* Wg_w = (const float*)d_in[11];
    const float* bg_w = (const float*)d_in[12];
    const float* Wc_w = (const float*)d_in[13];
    const float* bc_w = (const float*)d_in[14];
    const float* W1   = (const float*)d_in[15];
    const float* b1   = (const float*)d_in[16];
    const float* W2   = (const float*)d_in[17];
    const float* b2   = (const float*)d_in[18];
    float* out = (float*)d_out;

    float *char_x, *Xg_c, *Xc_c, *Hc, *RHc, *Uc;
    float *word_x, *Xg_w, *Xc_w, *Hw, *RHw, *Uw, *states, *hidden;
    cudaGetSymbolAddress((void**)&char_x, g_char_x);
    cudaGetSymbolAddress((void**)&Xg_c,   g_Xg_c);
    cudaGetSymbolAddress((void**)&Xc_c,   g_Xc_c);
    cudaGetSymbolAddress((void**)&Hc,     g_Hc);
    cudaGetSymbolAddress((void**)&RHc,    g_RHc);
    cudaGetSymbolAddress((void**)&Uc,     g_Uc);
    cudaGetSymbolAddress((void**)&word_x, g_word_x);
    cudaGetSymbolAddress((void**)&Xg_w,   g_Xg_w);
    cudaGetSymbolAddress((void**)&Xc_w,   g_Xc_w);
    cudaGetSymbolAddress((void**)&Hw,     g_Hw);
    cudaGetSymbolAddress((void**)&RHw,    g_RHw);
    cudaGetSymbolAddress((void**)&Uw,     g_Uw);
    cudaGetSymbolAddress((void**)&states, g_states);
    cudaGetSymbolAddress((void**)&hidden, g_hidden);

    // ---- char bi-GRU over unique word forms ----
    {
        int total = U_ * TC * CE;
        k_gather_char<<<(total + 255) / 256, 256>>>(charseqs, char_emb, char_x, total);
    }
    // x-projections (bias baked in)
    k_sgemm_bias<<<dim3((2 * H) / 64, (U_ * TC) / 64), 256>>>(
        char_x, Wg_c, bg_c, Xg_c, U_ * TC, 2 * H, CE, 0);
    k_sgemm_bias<<<dim3(H / 64, (U_ * TC) / 64), 256>>>(
        char_x, Wc_c, bc_c, Xc_c, U_ * TC, H, CE, 0);
    cudaMemsetAsync(Hc, 0, (size_t)2 * U_ * H * sizeof(float));

    const float* Wgh_c = Wg_c + (size_t)CE * 2 * H;  // recurrent slice of Wg_c
    const float* Wch_c = Wc_c + (size_t)CE * H;
    for (int t = 0; t < TC; t++) {
        k_gru_gates<<<dim3((2 * H) / 64, (2 * U_) / 64), 256>>>(
            Hc, Wgh_c, Xg_c, charseq_lens, RHc, Uc, U_, TC, t);
        k_gru_cand<<<dim3(H / 64, (2 * U_) / 64), 256>>>(
            Hc, Wch_c, Xc_c, charseq_lens, RHc, Uc, U_, TC, t);
    }

    // ---- word bi-GRU over sentences ----
    {
        int total = B_ * TW * WD;
        k_gather_word<<<(total + 255) / 256, 256>>>(charseq_ids, word_ids, word_emb, Hc, word_x);
    }
    k_sgemm_bias<<<dim3((2 * H) / 64, (B_ * TW) / 64), 256>>>(
        word_x, Wg_w, bg_w, Xg_w, B_ * TW, 2 * H, WD, 0);
    k_sgemm_bias<<<dim3(H / 64, (B_ * TW) / 64), 256>>>(
        word_x, Wc_w, bc_w, Xc_w, B_ * TW, H, WD, 0);
    cudaMemsetAsync(Hw, 0, (size_t)2 * B_ * H * sizeof(float));

    const float* Wgh_w = Wg_w + (size_t)WD * 2 * H;
    const float* Wch_w = Wc_w + (size_t)WD * H;
    for (int t = 0; t < TW; t++) {
        k_gru_gates<<<dim3((2 * H) / 64, (2 * B_) / 64), 256>>>(
            Hw, Wgh_w, Xg_w, sentence_lens, RHw, Uw, B_, TW, t);
        k_gru_cand<<<dim3(H / 64, (2 * B_) / 64), 256>>>(
            Hw, Wch_w, Xc_w, sentence_lens, RHw, Uw, B_, TW, t);
    }

    // ---- head: concat(fw,bw) -> leaky_relu FC 1024->64 -> FC 64->2 ----
    k_copy_states<<<(B_ * 2 * H + 255) / 256, 256>>>(Hw, states);
    k_sgemm_bias<<<dim3(1, B_ / 64), 256>>>(states, W1, b1, hidden, B_, 64, 2 * H, 1);
    k_fc2<<<(B_ * 2 + 255) / 256, 256>>>(hidden, W2, b2, out);
}

// round 2
// speedup vs baseline: 1.1259x; 1.1259x over previous
#include <cuda_runtime.h>
#include <math.h>

// Problem constants
#define H   512
#define CE  128
#define WE  256
#define U_  2048
#define TC  16
#define B_  256
#define TW  64
#define WD  (2*H + WE)   // 1280 word-input dim

// ---------------- scratch (device globals; allocation-free) ----------------
__device__ float g_char_x[(size_t)U_ * TC * CE];
__device__ float g_Xg_c[(size_t)U_ * TC * 2 * H];
__device__ float g_Xc_c[(size_t)U_ * TC * H];
__device__ float g_Hc [(size_t)2 * U_ * H];
__device__ float g_RHc[(size_t)2 * U_ * H];
__device__ float g_Uc [(size_t)2 * U_ * H];
__device__ float g_word_x[(size_t)B_ * TW * WD];
__device__ float g_Xg_w[(size_t)B_ * TW * 2 * H];
__device__ float g_Xc_w[(size_t)B_ * TW * H];
__device__ float g_Hw [(size_t)2 * B_ * H];
__device__ float g_RHw[(size_t)2 * B_ * H];
__device__ float g_Uw [(size_t)2 * B_ * H];
__device__ float g_states[(size_t)B_ * 2 * H];
__device__ float g_hidden[(size_t)B_ * 64];

// ============ big-tile fp32 GEMM core: BMxBN, 8x8/thread, float4 ============
// A[M,K] row-major (lda=K), B[K,N] row-major. K % 16 == 0, bm/bn tile-aligned.
template<int BM, int BN, int NT>
__device__ __forceinline__ void gemm_core(
    const float* __restrict__ A, const float* __restrict__ Bm,
    int K, int N, int bm, int bn,
    float acc[8][8], float As[16][BM], float Bs[16][BN])
{
    const int tid = threadIdx.x;
    const int tx = tid % (BN / 8);
    const int ty = tid / (BN / 8);
    constexpr int AL = (BM * 4) / NT;   // float4 loads of A per thread
    constexpr int BL = (BN * 4) / NT;
    float4 aR[AL], bR[BL];

    auto loadA = [&](int k0) {
        #pragma unroll
        for (int i = 0; i < AL; i++) {
            int idx = tid + i * NT;
            int r = idx >> 2, c4 = idx & 3;
            aR[i] = *(const float4*)(A + (size_t)(bm + r) * K + k0 + c4 * 4);
        }
    };
    auto loadB = [&](int k0) {
        #pragma unroll
        for (int i = 0; i < BL; i++) {
            int idx = tid + i * NT;
            int kr = idx / (BN / 4), c4 = idx % (BN / 4);
            bR[i] = *(const float4*)(Bm + (size_t)(k0 + kr) * N + bn + c4 * 4);
        }
    };
    auto storeA = [&]() {
        #pragma unroll
        for (int i = 0; i < AL; i++) {
            int idx = tid + i * NT;
            int r = idx >> 2, c4 = idx & 3;
            As[c4 * 4 + 0][r] = aR[i].x;
            As[c4 * 4 + 1][r] = aR[i].y;
            As[c4 * 4 + 2][r] = aR[i].z;
            As[c4 * 4 + 3][r] = aR[i].w;
        }
    };
    auto storeB = [&]() {
        #pragma unroll
        for (int i = 0; i < BL; i++) {
            int idx = tid + i * NT;
            int kr = idx / (BN / 4), c4 = idx % (BN / 4);
            *(float4*)&Bs[kr][c4 * 4] = bR[i];
        }
    };

    loadA(0); loadB(0);
    for (int k0 = 0;;) {
        storeA(); storeB();
        __syncthreads();
        int kn = k0 + 16;
        if (kn < K) { loadA(kn); loadB(kn); }  // prefetch next panel
        #pragma unroll
        for (int k = 0; k < 16; k++) {
            float4 a0 = *(const float4*)&As[k][ty * 4];
            float4 a1 = *(const float4*)&As[k][ty * 4 + BM / 2];
            float4 b0 = *(const float4*)&Bs[k][tx * 4];
            float4 b1 = *(const float4*)&Bs[k][tx * 4 + BN / 2];
            float av[8] = {a0.x, a0.y, a0.z, a0.w, a1.x, a1.y, a1.z, a1.w};
            float bv[8] = {b0.x, b0.y, b0.z, b0.w, b1.x, b1.y, b1.z, b1.w};
            #pragma unroll
            for (int i = 0; i < 8; i++)
                #pragma unroll
                for (int j = 0; j < 8; j++)
                    acc[i][j] = fmaf(av[i], bv[j], acc[i][j]);
        }
        k0 = kn;
        if (k0 >= K) break;
        __syncthreads();
    }
}

#define ROW8(i) (ty * 4 + ((i) & 3) + ((i) >> 2) * (BM / 2))
#define COL8(j) (tx * 4 + ((j) & 3) + ((j) >> 2) * (BN / 2))

// ---- big GEMM + bias (+optional leaky relu) ----
template<int BM, int BN, int NT>
__global__ void __launch_bounds__(NT)
k_sgemm_bias_t(const float* __restrict__ A, const float* __restrict__ Bm,
               const float* __restrict__ bias, float* __restrict__ C,
               int N, int K, int act)
{
    __shared__ float As[16][BM], Bs[16][BN];
    float acc[8][8] = {};
    int bm = blockIdx.y * BM, bn = blockIdx.x * BN;
    gemm_core<BM, BN, NT>(A, Bm, K, N, bm, bn, acc, As, Bs);
    int tx = threadIdx.x % (BN / 8), ty = threadIdx.x / (BN / 8);
    #pragma unroll
    for (int i = 0; i < 8; i++) {
        int r = bm + ROW8(i);
        #pragma unroll
        for (int j = 0; j < 8; j++) {
            int c = bn + COL8(j);
            float v = acc[i][j] + bias[c];
            if (act) v = v > 0.f ? v : 0.2f * v;
            C[(size_t)r * N + c] = v;
        }
    }
}

// ---- char GRU step 1 (big tile): gates = sigmoid(Xg[t] + H @ Wgh) ----
template<int BM, int BN, int NT>
__global__ void __launch_bounds__(NT)
k_gru_gates_t(const float* __restrict__ Hst, const float* __restrict__ Wgh,
              const float* __restrict__ Xg, const int* __restrict__ lens,
              float* __restrict__ RH, float* __restrict__ Ug,
              int Nseq, int T, int t)
{
    __shared__ float As[16][BM], Bs[16][BN];
    float acc[8][8] = {};
    int bm = blockIdx.y * BM, bn = blockIdx.x * BN;
    gemm_core<BM, BN, NT>(Hst, Wgh, H, 2 * H, bm, bn, acc, As, Bs);
    int tx = threadIdx.x % (BN / 8), ty = threadIdx.x / (BN / 8);
    bool isR = (bn + BN <= H);  // tile is entirely in the r-gate half
    #pragma unroll
    for (int i = 0; i < 8; i++) {
        int r = bm + ROW8(i);
        int dir = (r >= Nseq);
        int n = dir ? r - Nseq : r;
        int len = lens[n];
        int te = dir ? max(0, min(len - 1 - t, T - 1)) : t;
        const float* xg = Xg + ((size_t)n * T + te) * (2 * H);
        #pragma unroll
        for (int j = 0; j < 8; j++) {
            int c = bn + COL8(j);
            float g = 1.f / (1.f + __expf(-(xg[c] + acc[i][j])));
            if (isR) RH[(size_t)r * H + c] = g * Hst[(size_t)r * H + c];
            else     Ug[(size_t)r * H + (c - H)] = g;
        }
    }
}

// ---- char GRU step 2 (big tile): c = tanh(Xc[t] + (r*h) @ Wch); update ----
template<int BM, int BN, int NT>
__global__ void __launch_bounds__(NT)
k_gru_cand_t(float* __restrict__ Hst, const float* __restrict__ Wch,
             const float* __restrict__ Xc, const int* __restrict__ lens,
             const float* __restrict__ RH, const float* __restrict__ Ug,
             int Nseq, int T, int t)
{
    __shared__ float As[16][BM], Bs[16][BN];
    float acc[8][8] = {};
    int bm = blockIdx.y * BM, bn = blockIdx.x * BN;
    gemm_core<BM, BN, NT>(RH, Wch, H, H, bm, bn, acc, As, Bs);
    int tx = threadIdx.x % (BN / 8), ty = threadIdx.x / (BN / 8);
    #pragma unroll
    for (int i = 0; i < 8; i++) {
        int r = bm + ROW8(i);
        int dir = (r >= Nseq);
        int n = dir ? r - Nseq : r;
        int len = lens[n];
        if (t >= len) continue;  // h frozen past sequence end
        int te = dir ? max(0, min(len - 1 - t, T - 1)) : t;
        const float* xc = Xc + ((size_t)n * T + te) * H;
        #pragma unroll
        for (int j = 0; j < 8; j++) {
            int c = bn + COL8(j);
            float cc = tanhf(xc[c] + acc[i][j]);
            float h = Hst[(size_t)r * H + c];
            float u = Ug[(size_t)r * H + c];
            Hst[(size_t)r * H + c] = u * h + (1.f - u) * cc;
        }
    }
}

// ============ small 64x64 / 4x4 core for latency-bound word recurrence ======
__device__ __forceinline__ void gemm64(const float* __restrict__ A,
                                       const float* __restrict__ Bm,
                                       int K, int N, int bm, int bn,
                                       float acc[4][4]) {
    __shared__ float As[64][16];
    __shared__ float Bs[16][64];
    const int tid = threadIdx.x;
    const int tx = tid & 15;
    const int ty = tid >> 4;
    for (int k0 = 0; k0 < K; k0 += 16) {
        #pragma unroll
        for (int i = 0; i < 4; i++) {
            int idx = tid + i * 256;
            int ra = idx >> 4, ca = idx & 15;
            As[ra][ca] = A[(size_t)(bm + ra) * K + k0 + ca];
            int rb = idx >> 6, cb = idx & 63;
            Bs[rb][cb] = Bm[(size_t)(k0 + rb) * N + bn + cb];
        }
        __syncthreads();
        #pragma unroll
        for (int k = 0; k < 16; k++) {
            float a[4], b[4];
            #pragma unroll
            for (int i = 0; i < 4; i++) a[i] = As[ty + 16 * i][k];
            #pragma unroll
            for (int j = 0; j < 4; j++) b[j] = Bs[k][tx + 16 * j];
            #pragma unroll
            for (int i = 0; i < 4; i++)
                #pragma unroll
                for (int j = 0; j < 4; j++)
                    acc[i][j] = fmaf(a[i], b[j], acc[i][j]);
        }
        __syncthreads();
    }
}

__global__ __launch_bounds__(256)
void k_sgemm_bias_s(const float* __restrict__ A, const float* __restrict__ Bm,
                    const float* __restrict__ bias, float* __restrict__ C,
                    int M, int N, int K, int act) {
    float acc[4][4] = {};
    int bm = blockIdx.y * 64, bn = blockIdx.x * 64;
    gemm64(A, Bm, K, N, bm, bn, acc);
    const int tx = threadIdx.x & 15, ty = threadIdx.x >> 4;
    #pragma unroll
    for (int i = 0; i < 4; i++) {
        int r = bm + ty + 16 * i;
        #pragma unroll
        for (int j = 0; j < 4; j++) {
            int c = bn + tx + 16 * j;
            float v = acc[i][j] + bias[c];
            if (act) v = v > 0.f ? v : 0.2f * v;
            C[(size_t)r * N + c] = v;
        }
    }
}

__global__ __launch_bounds__(256)
void k_gru_gates_s(const float* __restrict__ Hst, const float* __restrict__ Wgh,
                   const float* __restrict__ Xg, const int* __restrict__ lens,
                   float* __restrict__ RH, float* __restrict__ Ug,
                   int Nseq, int T, int t) {
    float acc[4][4] = {};
    int bm = blockIdx.y * 64, bn = blockIdx.x * 64;
    gemm64(Hst, Wgh, H, 2 * H, bm, bn, acc);
    const int tx = threadIdx.x & 15, ty = threadIdx.x >> 4;
    bool isR = (bn + 64 <= H);
    #pragma unroll
    for (int i = 0; i < 4; i++) {
        int r = bm + ty + 16 * i;
        int dir = (r >= Nseq);
        int n = dir ? r - Nseq : r;
        int len = lens[n];
        int te = dir ? max(0, min(len - 1 - t, T - 1)) : t;
        const float* xg = Xg + ((size_t)n * T + te) * (2 * H);
        #pragma unroll
        for (int j = 0; j < 4; j++) {
            int c = bn + tx + 16 * j;
            float g = 1.f / (1.f + __expf(-(xg[c] + acc[i][j])));
            if (isR) RH[(size_t)r * H + c] = g * Hst[(size_t)r * H + c];
            else     Ug[(size_t)r * H + (c - H)] = g;
        }
    }
}

__global__ __launch_bounds__(256)
void k_gru_cand_s(float* __restrict__ Hst, const float* __restrict__ Wch,
                  const float* __restrict__ Xc, const int* __restrict__ lens,
                  const float* __restrict__ RH, const float* __restrict__ Ug,
                  int Nseq, int T, int t) {
    float acc[4][4] = {};
    int bm = blockIdx.y * 64, bn = blockIdx.x * 64;
    gemm64(RH, Wch, H, H, bm, bn, acc);
    const int tx = threadIdx.x & 15, ty = threadIdx.x >> 4;
    #pragma unroll
    for (int i = 0; i < 4; i++) {
        int r = bm + ty + 16 * i;
        int dir = (r >= Nseq);
        int n = dir ? r - Nseq : r;
        int len = lens[n];
        if (t >= len) continue;
        int te = dir ? max(0, min(len - 1 - t, T - 1)) : t;
        const float* xc = Xc + ((size_t)n * T + te) * H;
        #pragma unroll
        for (int j = 0; j < 4; j++) {
            int c = bn + tx + 16 * j;
            float cc = tanhf(xc[c] + acc[i][j]);
            float h = Hst[(size_t)r * H + c];
            float u = Ug[(size_t)r * H + c];
            Hst[(size_t)r * H + c] = u * h + (1.f - u) * cc;
        }
    }
}

// ---------------- gathers / small kernels -----------------------------------
__global__ void k_gather_char(const int* __restrict__ charseqs,
                              const float* __restrict__ char_emb,
                              float* __restrict__ out, int total) {
    int i = blockIdx.x * blockDim.x + threadIdx.x;
    if (i >= total) return;
    int c = i & (CE - 1);
    int w = i >> 7;
    int ch = charseqs[w];
    out[i] = char_emb[(size_t)ch * CE + c];
}

__global__ void k_gather_word(const int* __restrict__ cids,
                              const int* __restrict__ wids,
                              const float* __restrict__ word_emb,
                              const float* __restrict__ Hc,
                              float* __restrict__ out) {
    int i = blockIdx.x * blockDim.x + threadIdx.x;
    const int total = B_ * TW * WD;
    if (i >= total) return;
    int c = i % WD;
    int bt = i / WD;
    float v;
    if (c < H) {
        int id = cids[bt];
        v = Hc[(size_t)id * H + c];
    } else if (c < 2 * H) {
        int id = cids[bt];
        v = Hc[(size_t)(U_ + id) * H + (c - H)];
    } else {
        int w = wids[bt];
        v = word_emb[(size_t)w * WE + (c - 2 * H)];
    }
    out[i] = v;
}

__global__ void k_copy_states(const float* __restrict__ Hw, float* __restrict__ out) {
    int i = blockIdx.x * blockDim.x + threadIdx.x;
    if (i >= B_ * 2 * H) return;
    int c = i % (2 * H);
    int b = i / (2 * H);
    out[i] = (c < H) ? Hw[(size_t)b * H + c] : Hw[(size_t)(B_ + b) * H + (c - H)];
}

__global__ void k_fc2(const float* __restrict__ hidden, const float* __restrict__ W2,
                      const float* __restrict__ b2, float* __restrict__ out) {
    int i = blockIdx.x * blockDim.x + threadIdx.x;
    if (i >= B_ * 2) return;
    int b = i >> 1, j = i & 1;
    float s = b2[j];
    #pragma unroll
    for (int k = 0; k < 64; k++) s = fmaf(hidden[b * 64 + k], W2[k * 2 + j], s);
    out[i] = s;
}

// ---------------- host orchestration ----------------------------------------
extern "C" void kernel_launch(void* const* d_in, const int* in_sizes, int n_in,
                              void* d_out, int out_size) {
    const int*   charseqs      = (const int*)d_in[0];
    const int*   charseq_lens  = (const int*)d_in[1];
    const int*   charseq_ids   = (const int*)d_in[2];
    const int*   word_ids      = (const int*)d_in[3];
    const int*   sentence_lens = (const int*)d_in[4];
    const float* char_emb      = (const float*)d_in[5];
    const float* word_emb      = (const float*)d_in[6];
    const float* Wg_c = (const float*)d_in[7];
    const float* bg_c = (const float*)d_in[8];
    const float* Wc_c = (const float*)d_in[9];
    const float* bc_c = (const float*)d_in[10];
    const float* Wg_w = (const float*)d_in[11];
    const float* bg_w = (const float*)d_in[12];
    const float* Wc_w = (const float*)d_in[13];
    const float* bc_w = (const float*)d_in[14];
    const float* W1   = (const float*)d_in[15];
    const float* b1   = (const float*)d_in[16];
    const float* W2   = (const float*)d_in[17];
    const float* b2   = (const float*)d_in[18];
    float* out = (float*)d_out;

    float *char_x, *Xg_c, *Xc_c, *Hc, *RHc, *Uc;
    float *word_x, *Xg_w, *Xc_w, *Hw, *RHw, *Uw, *states, *hidden;
    cudaGetSymbolAddress((void**)&char_x, g_char_x);
    cudaGetSymbolAddress((void**)&Xg_c,   g_Xg_c);
    cudaGetSymbolAddress((void**)&Xc_c,   g_Xc_c);
    cudaGetSymbolAddress((void**)&Hc,     g_Hc);
    cudaGetSymbolAddress((void**)&RHc,    g_RHc);
    cudaGetSymbolAddress((void**)&Uc,     g_Uc);
    cudaGetSymbolAddress((void**)&word_x, g_word_x);
    cudaGetSymbolAddress((void**)&Xg_w,   g_Xg_w);
    cudaGetSymbolAddress((void**)&Xc_w,   g_Xc_w);
    cudaGetSymbolAddress((void**)&Hw,     g_Hw);
    cudaGetSymbolAddress((void**)&RHw,    g_RHw);
    cudaGetSymbolAddress((void**)&Uw,     g_Uw);
    cudaGetSymbolAddress((void**)&states, g_states);
    cudaGetSymbolAddress((void**)&hidden, g_hidden);

    // ---- char bi-GRU over unique word forms ----
    {
        int total = U_ * TC * CE;
        k_gather_char<<<(total + 255) / 256, 256>>>(charseqs, char_emb, char_x, total);
    }
    // x-projections (bias baked in): A = [U*TC, CE]
    k_sgemm_bias_t<128, 128, 256><<<dim3((2 * H) / 128, (U_ * TC) / 128), 256>>>(
        char_x, Wg_c, bg_c, Xg_c, 2 * H, CE, 0);
    k_sgemm_bias_t<128, 128, 256><<<dim3(H / 128, (U_ * TC) / 128), 256>>>(
        char_x, Wc_c, bc_c, Xc_c, H, CE, 0);
    cudaMemsetAsync(Hc, 0, (size_t)2 * U_ * H * sizeof(float));

    const float* Wgh_c = Wg_c + (size_t)CE * 2 * H;
    const float* Wch_c = Wc_c + (size_t)CE * H;
    for (int t = 0; t < TC; t++) {
        k_gru_gates_t<128, 128, 256><<<dim3((2 * H) / 128, (2 * U_) / 128), 256>>>(
            Hc, Wgh_c, Xg_c, charseq_lens, RHc, Uc, U_, TC, t);
        k_gru_cand_t<128, 128, 256><<<dim3(H / 128, (2 * U_) / 128), 256>>>(
            Hc, Wch_c, Xc_c, charseq_lens, RHc, Uc, U_, TC, t);
    }

    // ---- word bi-GRU over sentences ----
    {
        int total = B_ * TW * WD;
        k_gather_word<<<(total + 255) / 256, 256>>>(charseq_ids, word_ids, word_emb, Hc, word_x);
    }
    k_sgemm_bias_t<128, 128, 256><<<dim3((2 * H) / 128, (B_ * TW) / 128), 256>>>(
        word_x, Wg_w, bg_w, Xg_w, 2 * H, WD, 0);
    k_sgemm_bias_t<128, 128, 256><<<dim3(H / 128, (B_ * TW) / 128), 256>>>(
        word_x, Wc_w, bc_w, Xc_w, H, WD, 0);
    cudaMemsetAsync(Hw, 0, (size_t)2 * B_ * H * sizeof(float));

    // word recurrence: latency-bound (M=512) -> small 64x64/4x4 tiles
    const float* Wgh_w = Wg_w + (size_t)WD * 2 * H;
    const float* Wch_w = Wc_w + (size_t)WD * H;
    for (int t = 0; t < TW; t++) {
        k_gru_gates_s<<<dim3((2 * H) / 64, (2 * B_) / 64), 256>>>(
            Hw, Wgh_w, Xg_w, sentence_lens, RHw, Uw, B_, TW, t);
        k_gru_cand_s<<<dim3(H / 64, (2 * B_) / 64), 256>>>(
            Hw, Wch_w, Xc_w, sentence_lens, RHw, Uw, B_, TW, t);
    }

    // ---- head ----
    k_copy_states<<<(B_ * 2 * H + 255) / 256, 256>>>(Hw, states);
    k_sgemm_bias_s<<<dim3(1, B_ / 64), 256>>>(states, W1, b1, hidden, B_, 64, 2 * H, 1);
    k_fc2<<<(B_ * 2 + 255) / 256, 256>>>(hidden, W2, b2, out);
}

// round 3
// speedup vs baseline: 1.4095x; 1.2520x over previous
#include <cuda_runtime.h>
#include <math.h>

// Problem constants
#define H   512
#define CE  128
#define WE  256
#define U_  2048
#define TC  16
#define B_  256
#define TW  64
#define WD  (2*H + WE)   // 1280 word-input dim

// ---------------- scratch (device globals; allocation-free) ----------------
__device__ float g_char_x[(size_t)U_ * TC * CE];
__device__ float g_Xg_c[(size_t)U_ * TC * 2 * H];
__device__ float g_Xc_c[(size_t)U_ * TC * H];
__device__ float g_Hc [(size_t)2 * U_ * H];
__device__ float g_RHc[(size_t)2 * U_ * H];
__device__ float g_Uc [(size_t)2 * U_ * H];
__device__ float g_word_x[(size_t)B_ * TW * WD];
__device__ float g_Xg_w[(size_t)B_ * TW * 2 * H];
__device__ float g_Xc_w[(size_t)B_ * TW * H];
__device__ float g_Hw [(size_t)2 * B_ * H];
__device__ float g_RHw[(size_t)2 * B_ * H];
__device__ float g_Uw [(size_t)2 * B_ * H];
__device__ float g_states[(size_t)B_ * 2 * H];
__device__ float g_hidden[(size_t)B_ * 64];

// ---------------- packed f32x2 helpers --------------------------------------
__device__ __forceinline__ unsigned long long pk2(float x) {
    unsigned long long d;
    unsigned u = __float_as_uint(x);
    asm("mov.b64 %0, {%1, %1};" : "=l"(d) : "r"(u));
    return d;
}
__device__ __forceinline__ void ffma2(unsigned long long& d,
                                      unsigned long long a,
                                      unsigned long long b) {
    asm("fma.rn.f32x2 %0, %1, %2, %0;" : "+l"(d) : "l"(a), "l"(b));
}
__device__ __forceinline__ float lo2(unsigned long long v) { return __uint_as_float((unsigned)v); }
__device__ __forceinline__ float hi2(unsigned long long v) { return __uint_as_float((unsigned)(v >> 32)); }
__device__ __forceinline__ float pick2(unsigned long long v, int half) { return half ? hi2(v) : lo2(v); }

// ============ big-tile fp32 GEMM core: BMxBN, 8x8/thread, FFMA2 =============
// A[M,K] row-major, B[K,N] row-major. K % 16 == 0. NT = (BM/8)*(BN/8).
// acc[i][j] holds column pair; logical (i,q): row EROW(i), col ECOL(q),
// value = pick2(acc[i][q>>1], q&1).
template<int BM, int BN, int NT>
__device__ __forceinline__ void gemm_core2(const float* __restrict__ A,
                                           const float* __restrict__ Bm,
                                           int K, int N, int bm, int bn,
                                           unsigned long long acc[8][4]) {
    __shared__ float As[2][16][BM];
    __shared__ float Bs[2][16][BN];
    const int tid = threadIdx.x;
    const int tx = tid % (BN / 8);
    const int ty = tid / (BN / 8);
    constexpr int AL = (BM * 16) / (4 * NT);
    constexpr int BL = (BN * 16) / (4 * NT);
    float4 aR[AL], bR[BL];

    auto loadA = [&](int k0) {
        #pragma unroll
        for (int i = 0; i < AL; i++) {
            int idx = tid + i * NT;
            int r = idx >> 2, c4 = idx & 3;
            aR[i] = *(const float4*)(A + (size_t)(bm + r) * K + k0 + c4 * 4);
        }
    };
    auto loadB = [&](int k0) {
        #pragma unroll
        for (int i = 0; i < BL; i++) {
            int idx = tid + i * NT;
            int kr = idx / (BN / 4), c4 = idx % (BN / 4);
            bR[i] = *(const float4*)(Bm + (size_t)(k0 + kr) * N + bn + c4 * 4);
        }
    };
    auto stage = [&](int buf) {
        #pragma unroll
        for (int i = 0; i < AL; i++) {
            int idx = tid + i * NT;
            int r = idx >> 2, c4 = idx & 3;
            As[buf][c4 * 4 + 0][r] = aR[i].x;
            As[buf][c4 * 4 + 1][r] = aR[i].y;
            As[buf][c4 * 4 + 2][r] = aR[i].z;
            As[buf][c4 * 4 + 3][r] = aR[i].w;
        }
        #pragma unroll
        for (int i = 0; i < BL; i++) {
            int idx = tid + i * NT;
            int kr = idx / (BN / 4), c4 = idx % (BN / 4);
            *(float4*)&Bs[buf][kr][c4 * 4] = bR[i];
        }
    };

    loadA(0); loadB(0);
    stage(0);
    __syncthreads();
    int buf = 0;
    for (int k0 = 0;;) {
        int kn = k0 + 16;
        if (kn < K) { loadA(kn); loadB(kn); }
        #pragma unroll
        for (int k = 0; k < 16; k++) {
            float4 a0 = *(const float4*)&As[buf][k][ty * 4];
            float4 a1 = *(const float4*)&As[buf][k][ty * 4 + BM / 2];
            ulonglong2 b0 = *(const ulonglong2*)&Bs[buf][k][tx * 4];
            ulonglong2 b1 = *(const ulonglong2*)&Bs[buf][k][tx * 4 + BN / 2];
            unsigned long long bv[4] = {b0.x, b0.y, b1.x, b1.y};
            float av[8] = {a0.x, a0.y, a0.z, a0.w, a1.x, a1.y, a1.z, a1.w};
            #pragma unroll
            for (int i = 0; i < 8; i++) {
                unsigned long long ad = pk2(av[i]);
                #pragma unroll
                for (int j = 0; j < 4; j++) ffma2(acc[i][j], ad, bv[j]);
            }
        }
        if (kn >= K) break;
        stage(buf ^ 1);
        __syncthreads();
        buf ^= 1;
        k0 = kn;
    }
}

#define EROW(i) (ty * 4 + ((i) < 4 ? (i) : BM / 2 + (i) - 4))
#define ECOL(q) (tx * 4 + ((q) < 4 ? (q) : BN / 2 + (q) - 4))

// ---- big GEMM + bias (+optional leaky relu) ----
template<int BM, int BN, int NT>
__global__ void __launch_bounds__(NT)
k_sgemm_bias_t(const float* __restrict__ A, const float* __restrict__ Bm,
               const float* __restrict__ bias, float* __restrict__ C,
               int N, int K, int act)
{
    unsigned long long acc[8][4] = {};
    int bm = blockIdx.y * BM, bn = blockIdx.x * BN;
    gemm_core2<BM, BN, NT>(A, Bm, K, N, bm, bn, acc);
    int tx = threadIdx.x % (BN / 8), ty = threadIdx.x / (BN / 8);
    #pragma unroll
    for (int i = 0; i < 8; i++) {
        int r = bm + EROW(i);
        #pragma unroll
        for (int q = 0; q < 8; q++) {
            int c = bn + ECOL(q);
            float v = pick2(acc[i][q >> 1], q & 1) + bias[c];
            if (act) v = v > 0.f ? v : 0.2f * v;
            C[(size_t)r * N + c] = v;
        }
    }
}

// ---- char GRU step 1 (big tile): gates = sigmoid(Xg[t] + H @ Wgh) ----
template<int BM, int BN, int NT>
__global__ void __launch_bounds__(NT)
k_gru_gates_t(const float* __restrict__ Hst, const float* __restrict__ Wgh,
              const float* __restrict__ Xg, const int* __restrict__ lens,
              float* __restrict__ RH, float* __restrict__ Ug,
              int Nseq, int T, int t)
{
    unsigned long long acc[8][4] = {};
    int bm = blockIdx.y * BM, bn = blockIdx.x * BN;
    gemm_core2<BM, BN, NT>(Hst, Wgh, H, 2 * H, bm, bn, acc);
    int tx = threadIdx.x % (BN / 8), ty = threadIdx.x / (BN / 8);
    bool isR = (bn + BN <= H);  // BN divides H, so a tile never straddles
    #pragma unroll
    for (int i = 0; i < 8; i++) {
        int r = bm + EROW(i);
        int dir = (r >= Nseq);
        int n = dir ? r - Nseq : r;
        int len = lens[n];
        int te = dir ? max(0, min(len - 1 - t, T - 1)) : t;
        const float* xg = Xg + ((size_t)n * T + te) * (2 * H);
        #pragma unroll
        for (int q = 0; q < 8; q++) {
            int c = bn + ECOL(q);
            float g = 1.f / (1.f + __expf(-(xg[c] + pick2(acc[i][q >> 1], q & 1))));
            if (isR) RH[(size_t)r * H + c] = g * Hst[(size_t)r * H + c];
            else     Ug[(size_t)r * H + (c - H)] = g;
        }
    }
}

// ---- char GRU step 2 (big tile): c = tanh(Xc[t] + (r*h) @ Wch); update ----
template<int BM, int BN, int NT>
__global__ void __launch_bounds__(NT)
k_gru_cand_t(float* __restrict__ Hst, const float* __restrict__ Wch,
             const float* __restrict__ Xc, const int* __restrict__ lens,
             const float* __restrict__ RH, const float* __restrict__ Ug,
             int Nseq, int T, int t)
{
    unsigned long long acc[8][4] = {};
    int bm = blockIdx.y * BM, bn = blockIdx.x * BN;
    gemm_core2<BM, BN, NT>(RH, Wch, H, H, bm, bn, acc);
    int tx = threadIdx.x % (BN / 8), ty = threadIdx.x / (BN / 8);
    #pragma unroll
    for (int i = 0; i < 8; i++) {
        int r = bm + EROW(i);
        int dir = (r >= Nseq);
        int n = dir ? r - Nseq : r;
        int len = lens[n];
        if (t >= len) continue;  // h frozen past sequence end
        int te = dir ? max(0, min(len - 1 - t, T - 1)) : t;
        const float* xc = Xc + ((size_t)n * T + te) * H;
        #pragma unroll
        for (int q = 0; q < 8; q++) {
            int c = bn + ECOL(q);
            float cc = tanhf(xc[c] + pick2(acc[i][q >> 1], q & 1));
            float h = Hst[(size_t)r * H + c];
            float u = Ug[(size_t)r * H + c];
            Hst[(size_t)r * H + c] = u * h + (1.f - u) * cc;
        }
    }
}

// ============ small 64x64 / 4x4 FFMA2 core (word recurrence, head) ==========
__device__ __forceinline__ void gemm64_2(const float* __restrict__ A,
                                         const float* __restrict__ Bm,
                                         int K, int N, int bm, int bn,
                                         unsigned long long acc[4][2]) {
    __shared__ float As[2][16][64];
    __shared__ float Bs[2][16][64];
    const int tid = threadIdx.x;
    const int tx = tid & 15;
    const int ty = tid >> 4;
    float4 aR, bR;
    auto loadA = [&](int k0) {
        int r = tid >> 2, c4 = tid & 3;
        aR = *(const float4*)(A + (size_t)(bm + r) * K + k0 + c4 * 4);
    };
    auto loadB = [&](int k0) {
        int kr = tid >> 4, c4 = tid & 15;
        bR = *(const float4*)(Bm + (size_t)(k0 + kr) * N + bn + c4 * 4);
    };
    auto stage = [&](int buf) {
        int r = tid >> 2, c4 = tid & 3;
        As[buf][c4 * 4 + 0][r] = aR.x;
        As[buf][c4 * 4 + 1][r] = aR.y;
        As[buf][c4 * 4 + 2][r] = aR.z;
        As[buf][c4 * 4 + 3][r] = aR.w;
        int kr = tid >> 4, cb = tid & 15;
        *(float4*)&Bs[buf][kr][cb * 4] = bR;
    };
    loadA(0); loadB(0);
    stage(0);
    __syncthreads();
    int buf = 0;
    for (int k0 = 0;;) {
        int kn = k0 + 16;
        if (kn < K) { loadA(kn); loadB(kn); }
        #pragma unroll
        for (int k = 0; k < 16; k++) {
            float4 a = *(const float4*)&As[buf][k][ty * 4];
            ulonglong2 bp = *(const ulonglong2*)&Bs[buf][k][tx * 4];
            float av[4] = {a.x, a.y, a.z, a.w};
            #pragma unroll
            for (int i = 0; i < 4; i++) {
                unsigned long long ad = pk2(av[i]);
                ffma2(acc[i][0], ad, bp.x);
                ffma2(acc[i][1], ad, bp.y);
            }
        }
        if (kn >= K) break;
        stage(buf ^ 1);
        __syncthreads();
        buf ^= 1;
        k0 = kn;
    }
}

__global__ __launch_bounds__(256)
void k_sgemm_bias_s(const float* __restrict__ A, const float* __restrict__ Bm,
                    const float* __restrict__ bias, float* __restrict__ C,
                    int N, int K, int act) {
    unsigned long long acc[4][2] = {};
    int bm = blockIdx.y * 64, bn = blockIdx.x * 64;
    gemm64_2(A, Bm, K, N, bm, bn, acc);
    const int tx = threadIdx.x & 15, ty = threadIdx.x >> 4;
    #pragma unroll
    for (int i = 0; i < 4; i++) {
        int r = bm + ty * 4 + i;
        #pragma unroll
        for (int q = 0; q < 4; q++) {
            int c = bn + tx * 4 + q;
            float v = pick2(acc[i][q >> 1], q & 1) + bias[c];
            if (act) v = v > 0.f ? v : 0.2f * v;
            C[(size_t)r * N + c] = v;
        }
    }
}

__global__ __launch_bounds__(256)
void k_gru_gates_s(const float* __restrict__ Hst, const float* __restrict__ Wgh,
                   const float* __restrict__ Xg, const int* __restrict__ lens,
                   float* __restrict__ RH, float* __restrict__ Ug,
                   int Nseq, int T, int t) {
    unsigned long long acc[4][2] = {};
    int bm = blockIdx.y * 64, bn = blockIdx.x * 64;
    gemm64_2(Hst, Wgh, H, 2 * H, bm, bn, acc);
    const int tx = threadIdx.x & 15, ty = threadIdx.x >> 4;
    bool isR = (bn + 64 <= H);
    #pragma unroll
    for (int i = 0; i < 4; i++) {
        int r = bm + ty * 4 + i;
        int dir = (r >= Nseq);
        int n = dir ? r - Nseq : r;
        int len = lens[n];
        int te = dir ? max(0, min(len - 1 - t, T - 1)) : t;
        const float* xg = Xg + ((size_t)n * T + te) * (2 * H);
        #pragma unroll
        for (int q = 0; q < 4; q++) {
            int c = bn + tx * 4 + q;
            float g = 1.f / (1.f + __expf(-(xg[c] + pick2(acc[i][q >> 1], q & 1))));
            if (isR) RH[(size_t)r * H + c] = g * Hst[(size_t)r * H + c];
            else     Ug[(size_t)r * H + (c - H)] = g;
        }
    }
}

__global__ __launch_bounds__(256)
void k_gru_cand_s(float* __restrict__ Hst, const float* __restrict__ Wch,
                  const float* __restrict__ Xc, const int* __restrict__ lens,
                  const float* __restrict__ RH, const float* __restrict__ Ug,
                  int Nseq, int T, int t) {
    unsigned long long acc[4][2] = {};
    int bm = blockIdx.y * 64, bn = blockIdx.x * 64;
    gemm64_2(RH, Wch, H, H, bm, bn, acc);
    const int tx = threadIdx.x & 15, ty = threadIdx.x >> 4;
    #pragma unroll
    for (int i = 0; i < 4; i++) {
        int r = bm + ty * 4 + i;
        int dir = (r >= Nseq);
        int n = dir ? r - Nseq : r;
        int len = lens[n];
        if (t >= len) continue;
        int te = dir ? max(0, min(len - 1 - t, T - 1)) : t;
        const float* xc = Xc + ((size_t)n * T + te) * H;
        #pragma unroll
        for (int q = 0; q < 4; q++) {
            int c = bn + tx * 4 + q;
            float cc = tanhf(xc[c] + pick2(acc[i][q >> 1], q & 1));
            float h = Hst[(size_t)r * H + c];
            float u = Ug[(size_t)r * H + c];
            Hst[(size_t)r * H + c] = u * h + (1.f - u) * cc;
        }
    }
}

// ---------------- gathers / small kernels -----------------------------------
__global__ void k_gather_char(const int* __restrict__ charseqs,
                              const float* __restrict__ char_emb,
                              float* __restrict__ out, int total) {
    int i = blockIdx.x * blockDim.x + threadIdx.x;
    if (i >= total) return;
    int c = i & (CE - 1);
    int w = i >> 7;
    int ch = charseqs[w];
    out[i] = char_emb[(size_t)ch * CE + c];
}

__global__ void k_gather_word(const int* __restrict__ cids,
                              const int* __restrict__ wids,
                              const float* __restrict__ word_emb,
                              const float* __restrict__ Hc,
                              float* __restrict__ out) {
    int i = blockIdx.x * blockDim.x + threadIdx.x;
    const int total = B_ * TW * WD;
    if (i >= total) return;
    int c = i % WD;
    int bt = i / WD;
    float v;
    if (c < H) {
        int id = cids[bt];
        v = Hc[(size_t)id * H + c];
    } else if (c < 2 * H) {
        int id = cids[bt];
        v = Hc[(size_t)(U_ + id) * H + (c - H)];
    } else {
        int w = wids[bt];
        v = word_emb[(size_t)w * WE + (c - 2 * H)];
    }
    out[i] = v;
}

__global__ void k_copy_states(const float* __restrict__ Hw, float* __restrict__ out) {
    int i = blockIdx.x * blockDim.x + threadIdx.x;
    if (i >= B_ * 2 * H) return;
    int c = i % (2 * H);
    int b = i / (2 * H);
    out[i] = (c < H) ? Hw[(size_t)b * H + c] : Hw[(size_t)(B_ + b) * H + (c - H)];
}

__global__ void k_fc2(const float* __restrict__ hidden, const float* __restrict__ W2,
                      const float* __restrict__ b2, float* __restrict__ out) {
    int i = blockIdx.x * blockDim.x + threadIdx.x;
    if (i >= B_ * 2) return;
    int b = i >> 1, j = i & 1;
    float s = b2[j];
    #pragma unroll
    for (int k = 0; k < 64; k++) s = fmaf(hidden[b * 64 + k], W2[k * 2 + j], s);
    out[i] = s;
}

// ---------------- host orchestration ----------------------------------------
extern "C" void kernel_launch(void* const* d_in, const int* in_sizes, int n_in,
                              void* d_out, int out_size) {
    const int*   charseqs      = (const int*)d_in[0];
    const int*   charseq_lens  = (const int*)d_in[1];
    const int*   charseq_ids   = (const int*)d_in[2];
    const int*   word_ids      = (const int*)d_in[3];
    const int*   sentence_lens = (const int*)d_in[4];
    const float* char_emb      = (const float*)d_in[5];
    const float* word_emb      = (const float*)d_in[6];
    const float* Wg_c = (const float*)d_in[7];
    const float* bg_c = (const float*)d_in[8];
    const float* Wc_c = (const float*)d_in[9];
    const float* bc_c = (const float*)d_in[10];
    const float* Wg_w = (const float*)d_in[11];
    const float* bg_w = (const float*)d_in[12];
    const float* Wc_w = (const float*)d_in[13];
    const float* bc_w = (const float*)d_in[14];
    const float* W1   = (const float*)d_in[15];
    const float* b1   = (const float*)d_in[16];
    const float* W2   = (const float*)d_in[17];
    const float* b2   = (const float*)d_in[18];
    float* out = (float*)d_out;

    float *char_x, *Xg_c, *Xc_c, *Hc, *RHc, *Uc;
    float *word_x, *Xg_w, *Xc_w, *Hw, *RHw, *Uw, *states, *hidden;
    cudaGetSymbolAddress((void**)&char_x, g_char_x);
    cudaGetSymbolAddress((void**)&Xg_c,   g_Xg_c);
    cudaGetSymbolAddress((void**)&Xc_c,   g_Xc_c);
    cudaGetSymbolAddress((void**)&Hc,     g_Hc);
    cudaGetSymbolAddress((void**)&RHc,    g_RHc);
    cudaGetSymbolAddress((void**)&Uc,     g_Uc);
    cudaGetSymbolAddress((void**)&word_x, g_word_x);
    cudaGetSymbolAddress((void**)&Xg_w,   g_Xg_w);
    cudaGetSymbolAddress((void**)&Xc_w,   g_Xc_w);
    cudaGetSymbolAddress((void**)&Hw,     g_Hw);
    cudaGetSymbolAddress((void**)&RHw,    g_RHw);
    cudaGetSymbolAddress((void**)&Uw,     g_Uw);
    cudaGetSymbolAddress((void**)&states, g_states);
    cudaGetSymbolAddress((void**)&hidden, g_hidden);

    // ---- char bi-GRU over unique word forms ----
    {
        int total = U_ * TC * CE;
        k_gather_char<<<(total + 255) / 256, 256>>>(charseqs, char_emb, char_x, total);
    }
    // x-projections (bias baked in): A = [U*TC, 128]
    k_sgemm_bias_t<128, 256, 512><<<dim3((2 * H) / 256, (U_ * TC) / 128), 512>>>(
        char_x, Wg_c, bg_c, Xg_c, 2 * H, CE, 0);
    k_sgemm_bias_t<128, 128, 256><<<dim3(H / 128, (U_ * TC) / 128), 256>>>(
        char_x, Wc_c, bc_c, Xc_c, H, CE, 0);
    cudaMemsetAsync(Hc, 0, (size_t)2 * U_ * H * sizeof(float));

    const float* Wgh_c = Wg_c + (size_t)CE * 2 * H;
    const float* Wch_c = Wc_c + (size_t)CE * H;
    for (int t = 0; t < TC; t++) {
        // gates: grid (4, 32) = 128 CTAs = one full wave
        k_gru_gates_t<128, 256, 512><<<dim3((2 * H) / 256, (2 * U_) / 128), 512>>>(
            Hc, Wgh_c, Xg_c, charseq_lens, RHc, Uc, U_, TC, t);
        // cand: grid (4, 32) = 128 CTAs
        k_gru_cand_t<128, 128, 256><<<dim3(H / 128, (2 * U_) / 128), 256>>>(
            Hc, Wch_c, Xc_c, charseq_lens, RHc, Uc, U_, TC, t);
    }

    // ---- word bi-GRU over sentences ----
    {
        int total = B_ * TW * WD;
        k_gather_word<<<(total + 255) / 256, 256>>>(charseq_ids, word_ids, word_emb, Hc, word_x);
    }
    k_sgemm_bias_t<128, 256, 512><<<dim3((2 * H) / 256, (B_ * TW) / 128), 512>>>(
        word_x, Wg_w, bg_w, Xg_w, 2 * H, WD, 0);
    k_sgemm_bias_t<128, 128, 256><<<dim3(H / 128, (B_ * TW) / 128), 256>>>(
        word_x, Wc_w, bc_w, Xc_w, H, WD, 0);
    cudaMemsetAsync(Hw, 0, (size_t)2 * B_ * H * sizeof(float));

    // word recurrence: parallelism-limited (M=512) -> 64x64 tiles
    const float* Wgh_w = Wg_w + (size_t)WD * 2 * H;
    const float* Wch_w = Wc_w + (size_t)WD * H;
    for (int t = 0; t < TW; t++) {
        k_gru_gates_s<<<dim3((2 * H) / 64, (2 * B_) / 64), 256>>>(
            Hw, Wgh_w, Xg_w, sentence_lens, RHw, Uw, B_, TW, t);
        k_gru_cand_s<<<dim3(H / 64, (2 * B_) / 64), 256>>>(
            Hw, Wch_w, Xc_w, sentence_lens, RHw, Uw, B_, TW, t);
    }

    // ---- head ----
    k_copy_states<<<(B_ * 2 * H + 255) / 256, 256>>>(Hw, states);
    k_sgemm_bias_s<<<dim3(1, B_ / 64), 256>>>(states, W1, b1, hidden, 64, 2 * H, 1);
    k_fc2<<<(B_ * 2 + 255) / 256, 256>>>(hidden, W2, b2, out);
}

// round 5
// speedup vs baseline: 1.7568x; 1.2463x over previous
#include <cuda_runtime.h>
#include <cuda_bf16.h>
#include <math.h>
#include <stdint.h>

// Problem constants
#define H   512
#define CE  128
#define WE  256
#define U_  2048
#define TC  16
#define B_  256
#define TW  64
#define WD  (2*H + WE)   // 1280 word-input dim

// ---------------- scratch (device globals; allocation-free) ----------------
__device__ float g_Xg_c[(size_t)U_ * TC * 2 * H];
__device__ float g_Xc_c[(size_t)U_ * TC * H];
__device__ float g_Hc [(size_t)2 * U_ * H];
__device__ float g_Uc [(size_t)2 * U_ * H];
__device__ float g_Xg_w[(size_t)B_ * TW * 2 * H];
__device__ float g_Xc_w[(size_t)B_ * TW * H];
__device__ float g_Hw [(size_t)2 * B_ * H];
__device__ float g_RHw[(size_t)2 * B_ * H];
__device__ float g_Uw [(size_t)2 * B_ * H];
__device__ float g_states[(size_t)B_ * 2 * H];
__device__ float g_hidden[(size_t)B_ * 64];

// split-bf16 A-operand images (tiled 128x32)
__device__ __align__(16) __nv_bfloat16 g_cAh[(size_t)U_ * TC * CE];
__device__ __align__(16) __nv_bfloat16 g_cAl[(size_t)U_ * TC * CE];
__device__ __align__(16) __nv_bfloat16 g_wAh[(size_t)B_ * TW * WD];
__device__ __align__(16) __nv_bfloat16 g_wAl[(size_t)B_ * TW * WD];
__device__ __align__(16) __nv_bfloat16 g_Hch[(size_t)2 * U_ * H];
__device__ __align__(16) __nv_bfloat16 g_Hcl[(size_t)2 * U_ * H];
__device__ __align__(16) __nv_bfloat16 g_RHh[(size_t)2 * U_ * H];
__device__ __align__(16) __nv_bfloat16 g_RHl[(size_t)2 * U_ * H];
// split-bf16 weights ([N,K] k-major tiled 128x32)
__device__ __align__(16) __nv_bfloat16 g_Wgc_h[(size_t)CE * 1024], g_Wgc_l[(size_t)CE * 1024];
__device__ __align__(16) __nv_bfloat16 g_Wcc_h[(size_t)CE * 512],  g_Wcc_l[(size_t)CE * 512];
__device__ __align__(16) __nv_bfloat16 g_Wgw_h[(size_t)WD * 1024], g_Wgw_l[(size_t)WD * 1024];
__device__ __align__(16) __nv_bfloat16 g_Wcw_h[(size_t)WD * 512],  g_Wcw_l[(size_t)WD * 512];
__device__ __align__(16) __nv_bfloat16 g_Wghc_h[(size_t)H * 1024], g_Wghc_l[(size_t)H * 1024];
__device__ __align__(16) __nv_bfloat16 g_Wchc_h[(size_t)H * 512],  g_Wchc_l[(size_t)H * 512];

// ---------------- helpers ----------------------------------------------------
__device__ __forceinline__ uint32_t smem_u32(const void* p) {
    uint32_t a;
    asm("{ .reg .u64 t; cvta.to.shared.u64 t, %1; cvt.u32.u64 %0, t; }" : "=r"(a) : "l"(p));
    return a;
}
__device__ __forceinline__ void split2(float v, __nv_bfloat16& h, __nv_bfloat16& l) {
    h = __float2bfloat16(v);
    l = __float2bfloat16(v - __bfloat162float(h));
}
// tiled element offset: row-major 128x32 tiles
__device__ __forceinline__ size_t tiled_off(int row, int col, int NKt) {
    return ((size_t)((row >> 7) * NKt + (col >> 5)) * 128 + (row & 127)) * 32 + (col & 31);
}
__device__ __forceinline__ void ldm4(uint32_t r[4], uint32_t saddr) {
    asm volatile("ldmatrix.sync.aligned.m8n8.x4.shared.b16 {%0,%1,%2,%3}, [%4];"
                 : "=r"(r[0]), "=r"(r[1]), "=r"(r[2]), "=r"(r[3]) : "r"(saddr));
}
__device__ __forceinline__ void mma16816(float c[4], const uint32_t a[4], const uint32_t b[2]) {
    asm volatile(
        "mma.sync.aligned.m16n8k16.row.col.f32.bf16.bf16.f32 "
        "{%0,%1,%2,%3},{%4,%5,%6,%7},{%8,%9},{%0,%1,%2,%3};"
        : "+f"(c[0]), "+f"(c[1]), "+f"(c[2]), "+f"(c[3])
        : "r"(a[0]), "r"(a[1]), "r"(a[2]), "r"(a[3]), "r"(b[0]), "r"(b[1]));
}

// packed f32x2 (FFMA2) helpers for the scalar path
__device__ __forceinline__ unsigned long long pk2(float x) {
    unsigned long long d;
    unsigned u = __float_as_uint(x);
    asm("mov.b64 %0, {%1, %1};" : "=l"(d) : "r"(u));
    return d;
}
__device__ __forceinline__ void ffma2(unsigned long long& d,
                                      unsigned long long a,
                                      unsigned long long b) {
    asm("fma.rn.f32x2 %0, %1, %2, %0;" : "+l"(d) : "l"(a), "l"(b));
}
__device__ __forceinline__ float pick2(unsigned long long v, int half) {
    return __uint_as_float(half ? (unsigned)(v >> 32) : (unsigned)v);
}

// =============== split-bf16 mma.sync core: 128x128 tile, 256 thr ============
// A,B given as split tiled images (128x32 tiles). Fills acc[mi][ni][4].
__device__ __forceinline__ void mma_core(
    const __nv_bfloat16* __restrict__ Ah, const __nv_bfloat16* __restrict__ Al,
    const __nv_bfloat16* __restrict__ Bh, const __nv_bfloat16* __restrict__ Bl,
    int NKt, int mt, int nt, float acc[4][4][4])
{
    __shared__ __align__(16) __nv_bfloat16 sA[2][128][40];
    __shared__ __align__(16) __nv_bfloat16 sB[2][128][40];
    const int tid = threadIdx.x, lane = tid & 31, warp = tid >> 5;
    const int wy = warp >> 2, wx = warp & 3;
    const int gq = lane >> 3, rr = lane & 7;   // ldmatrix addressing
    uint4 pA[2][2], pB[2][2];

    auto gload = [&](int c) {
        #pragma unroll
        for (int i = 0; i < 2; i++) {
            int idx = tid + i * 256;
            int r = idx >> 2, c8 = idx & 3;
            size_t ta = ((size_t)(mt * NKt + c) * 128 + r) * 32 + c8 * 8;
            size_t tb = ((size_t)(nt * NKt + c) * 128 + r) * 32 + c8 * 8;
            pA[0][i] = *(const uint4*)(Ah + ta);
            pA[1][i] = *(const uint4*)(Al + ta);
            pB[0][i] = *(const uint4*)(Bh + tb);
            pB[1][i] = *(const uint4*)(Bl + tb);
        }
    };
    auto sstore = [&]() {
        #pragma unroll
        for (int i = 0; i < 2; i++) {
            int idx = tid + i * 256;
            int r = idx >> 2, c8 = idx & 3;
            *(uint4*)&sA[0][r][c8 * 8] = pA[0][i];
            *(uint4*)&sA[1][r][c8 * 8] = pA[1][i];
            *(uint4*)&sB[0][r][c8 * 8] = pB[0][i];
            *(uint4*)&sB[1][r][c8 * 8] = pB[1][i];
        }
    };
    const uint32_t bAh = smem_u32(&sA[0][0][0]), bAl = smem_u32(&sA[1][0][0]);
    const uint32_t bBh = smem_u32(&sB[0][0][0]), bBl = smem_u32(&sB[1][0][0]);

    gload(0);
    for (int c = 0;;) {
        sstore();
        __syncthreads();
        int cn = c + 1;
        if (cn < NKt) gload(cn);
        #pragma unroll
        for (int s = 0; s < 2; s++) {
            uint32_t ah[4][4], al[4][4], bh[4][2], bl[4][2];
            #pragma unroll
            for (int mi = 0; mi < 4; mi++) {
                int row = wy * 64 + mi * 16 + (gq & 1) * 8 + rr;
                int col = s * 16 + (gq >> 1) * 8;
                uint32_t off = (uint32_t)(row * 40 + col) * 2;
                ldm4(ah[mi], bAh + off);
                ldm4(al[mi], bAl + off);
            }
            #pragma unroll
            for (int nb = 0; nb < 2; nb++) {
                int nrow = wx * 32 + nb * 16 + (gq >> 1) * 8 + rr;
                int col = s * 16 + (gq & 1) * 8;
                uint32_t off = (uint32_t)(nrow * 40 + col) * 2;
                uint32_t t0[4], t1[4];
                ldm4(t0, bBh + off);
                ldm4(t1, bBl + off);
                bh[nb * 2][0] = t0[0]; bh[nb * 2][1] = t0[1];
                bh[nb * 2 + 1][0] = t0[2]; bh[nb * 2 + 1][1] = t0[3];
                bl[nb * 2][0] = t1[0]; bl[nb * 2][1] = t1[1];
                bl[nb * 2 + 1][0] = t1[2]; bl[nb * 2 + 1][1] = t1[3];
            }
            #pragma unroll
            for (int mi = 0; mi < 4; mi++)
                #pragma unroll
                for (int ni = 0; ni < 4; ni++) {
                    mma16816(acc[mi][ni], ah[mi], bh[ni]);
                    mma16816(acc[mi][ni], ah[mi], bl[ni]);
                    mma16816(acc[mi][ni], al[mi], bh[ni]);
                }
        }
        __syncthreads();
        c = cn;
        if (c >= NKt) break;
    }
}

// ---- GEMM + bias (x-projections): C[M,Nd] fp32 = A@W + bias ----
__global__ void __launch_bounds__(256)
k_mm_bias(const __nv_bfloat16* __restrict__ Ah, const __nv_bfloat16* __restrict__ Al,
          const __nv_bfloat16* __restrict__ Bh, const __nv_bfloat16* __restrict__ Bl,
          const float* __restrict__ bias, float* __restrict__ C, int Nd, int NKt)
{
    float acc[4][4][4] = {};
    int nt = blockIdx.x, mt = blockIdx.y;
    mma_core(Ah, Al, Bh, Bl, NKt, mt, nt, acc);
    int lane = threadIdx.x & 31, warp = threadIdx.x >> 5;
    int wy = warp >> 2, wx = warp & 3;
    int bm = mt * 128, bn = nt * 128;
    #pragma unroll
    for (int mi = 0; mi < 4; mi++) {
        #pragma unroll
        for (int ni = 0; ni < 4; ni++) {
            int n0 = bn + wx * 32 + ni * 8 + (lane & 3) * 2;
            int r0 = bm + wy * 64 + mi * 16 + (lane >> 2);
            float2 v0 = {acc[mi][ni][0] + bias[n0], acc[mi][ni][1] + bias[n0 + 1]};
            float2 v1 = {acc[mi][ni][2] + bias[n0], acc[mi][ni][3] + bias[n0 + 1]};
            *(float2*)(C + (size_t)r0 * Nd + n0) = v0;
            *(float2*)(C + (size_t)(r0 + 8) * Nd + n0) = v1;
        }
    }
}

// ---- char GRU gates (tensor): g = sigmoid(Xg[t] + H @ Wgh) ----
// writes RH split image (r-half) and Ug fp32 (u-half)
__global__ void __launch_bounds__(256)
k_gates_mma(const __nv_bfloat16* __restrict__ Hh, const __nv_bfloat16* __restrict__ Hl,
            const __nv_bfloat16* __restrict__ Wh, const __nv_bfloat16* __restrict__ Wl,
            const float* __restrict__ Xg, const int* __restrict__ lens,
            const float* __restrict__ Hfp,
            __nv_bfloat16* __restrict__ RHh, __nv_bfloat16* __restrict__ RHl,
            float* __restrict__ Ug, int Nseq, int T, int t)
{
    float acc[4][4][4] = {};
    int nt = blockIdx.x, mt = blockIdx.y;
    mma_core(Hh, Hl, Wh, Wl, H / 32, mt, nt, acc);
    int lane = threadIdx.x & 31, warp = threadIdx.x >> 5;
    int wy = warp >> 2, wx = warp & 3;
    int bm = mt * 128, bn = nt * 128;
    bool isR = (bn + 128 <= H);
    #pragma unroll
    for (int mi = 0; mi < 4; mi++) {
        #pragma unroll
        for (int hh = 0; hh < 2; hh++) {
            int r = bm + wy * 64 + mi * 16 + (lane >> 2) + hh * 8;
            int dir = (r >= Nseq);
            int n = dir ? r - Nseq : r;
            int len = lens[n];
            int te = dir ? max(0, min(len - 1 - t, T - 1)) : t;
            const float* xg = Xg + ((size_t)n * T + te) * (2 * H);
            #pragma unroll
            for (int ni = 0; ni < 4; ni++) {
                int c0 = bn + wx * 32 + ni * 8 + (lane & 3) * 2;
                float a0 = acc[mi][ni][hh * 2 + 0];
                float a1 = acc[mi][ni][hh * 2 + 1];
                float g0 = 1.f / (1.f + __expf(-(xg[c0] + a0)));
                float g1 = 1.f / (1.f + __expf(-(xg[c0 + 1] + a1)));
                if (isR) {
                    float rh0 = g0 * Hfp[(size_t)r * H + c0];
                    float rh1 = g1 * Hfp[(size_t)r * H + c0 + 1];
                    __nv_bfloat16 h0, l0, h1, l1;
                    split2(rh0, h0, l0);
                    split2(rh1, h1, l1);
                    size_t o = tiled_off(r, c0, H / 32);
                    RHh[o] = h0; RHl[o] = l0;
                    RHh[o + 1] = h1; RHl[o + 1] = l1;
                } else {
                    Ug[(size_t)r * H + (c0 - H)] = g0;
                    Ug[(size_t)r * H + (c0 - H) + 1] = g1;
                }
            }
        }
    }
}

// ---- char GRU cand (tensor): c = tanh(Xc[t] + RH @ Wch); h update ----
__global__ void __launch_bounds__(256)
k_cand_mma(const __nv_bfloat16* __restrict__ RHh, const __nv_bfloat16* __restrict__ RHl,
           const __nv_bfloat16* __restrict__ Wh, const __nv_bfloat16* __restrict__ Wl,
           const float* __restrict__ Xc, const int* __restrict__ lens,
           float* __restrict__ Hfp, const float* __restrict__ Ug,
           __nv_bfloat16* __restrict__ Hh, __nv_bfloat16* __restrict__ Hl,
           int Nseq, int T, int t)
{
    float acc[4][4][4] = {};
    int nt = blockIdx.x, mt = blockIdx.y;
    mma_core(RHh, RHl, Wh, Wl, H / 32, mt, nt, acc);
    int lane = threadIdx.x & 31, warp = threadIdx.x >> 5;
    int wy = warp >> 2, wx = warp & 3;
    int bm = mt * 128, bn = nt * 128;
    #pragma unroll
    for (int mi = 0; mi < 4; mi++) {
        #pragma unroll
        for (int hh = 0; hh < 2; hh++) {
            int r = bm + wy * 64 + mi * 16 + (lane >> 2) + hh * 8;
            int dir = (r >= Nseq);
            int n = dir ? r - Nseq : r;
            int len = lens[n];
            if (t >= len) continue;   // frozen
            int te = dir ? max(0, min(len - 1 - t, T - 1)) : t;
            const float* xc = Xc + ((size_t)n * T + te) * H;
            #pragma unroll
            for (int ni = 0; ni < 4; ni++) {
                int c0 = bn + wx * 32 + ni * 8 + (lane & 3) * 2;
                #pragma unroll
                for (int q = 0; q < 2; q++) {
                    int c = c0 + q;
                    float cc = tanhf(xc[c] + acc[mi][ni][hh * 2 + q]);
                    float h = Hfp[(size_t)r * H + c];
                    float u = Ug[(size_t)r * H + c];
                    float hn = u * h + (1.f - u) * cc;
                    Hfp[(size_t)r * H + c] = hn;
                    __nv_bfloat16 bh, bl;
                    split2(hn, bh, bl);
                    size_t o = tiled_off(r, c, H / 32);
                    Hh[o] = bh; Hl[o] = bl;
                }
            }
        }
    }
}

// ---- one-time weight split into [N,K] k-major tiled 128x32 ----
__global__ void k_prep_w(const float* __restrict__ W, int Kx, int Nd,
                         __nv_bfloat16* __restrict__ Bh, __nv_bfloat16* __restrict__ Bl) {
    int i = blockIdx.x * blockDim.x + threadIdx.x;
    if (i >= Kx * Nd) return;
    int k = i / Nd, n = i % Nd;
    __nv_bfloat16 h, l;
    split2(W[i], h, l);
    int NKt = Kx >> 5;
    size_t off = ((size_t)((n >> 7) * NKt + (k >> 5)) * 128 + (n & 127)) * 32 + (k & 31);
    Bh[off] = h; Bl[off] = l;
}

// ---- gathers emitting split tiled A ----------------------------------------
__global__ void k_gather_char_sp(const int* __restrict__ charseqs,
                                 const float* __restrict__ char_emb,
                                 __nv_bfloat16* __restrict__ Ah,
                                 __nv_bfloat16* __restrict__ Al, int total) {
    int i = blockIdx.x * blockDim.x + threadIdx.x;
    if (i >= total) return;
    int c = i & (CE - 1);
    int rowg = i >> 7;
    float v = char_emb[(size_t)charseqs[rowg] * CE + c];
    __nv_bfloat16 h, l;
    split2(v, h, l);
    size_t off = tiled_off(rowg, c, CE / 32);
    Ah[off] = h; Al[off] = l;
}

__global__ void k_gather_word_sp(const int* __restrict__ cids,
                                 const int* __restrict__ wids,
                                 const float* __restrict__ word_emb,
                                 const float* __restrict__ Hc,
                                 __nv_bfloat16* __restrict__ Ah,
                                 __nv_bfloat16* __restrict__ Al) {
    int i = blockIdx.x * blockDim.x + threadIdx.x;
    const int total = B_ * TW * WD;
    if (i >= total) return;
    int c = i % WD;
    int bt = i / WD;
    float v;
    if (c < H) {
        v = Hc[(size_t)cids[bt] * H + c];
    } else if (c < 2 * H) {
        v = Hc[(size_t)(U_ + cids[bt]) * H + (c - H)];
    } else {
        v = word_emb[(size_t)wids[bt] * WE + (c - 2 * H)];
    }
    __nv_bfloat16 h, l;
    split2(v, h, l);
    size_t off = tiled_off(bt, c, WD / 32);
    Ah[off] = h; Al[off] = l;
}

// ============ small 64x64 / 4x4 FFMA2 core (word recurrence, head) ==========
__device__ __forceinline__ void gemm64_2(const float* __restrict__ A,
                                         const float* __restrict__ Bm,
                                         int K, int N, int bm, int bn,
                                         unsigned long long acc[4][2]) {
    __shared__ float As[2][16][64];
    __shared__ float Bs[2][16][64];
    const int tid = threadIdx.x;
    const int tx = tid & 15;
    const int ty = tid >> 4;
    float4 aR, bR;
    auto loadA = [&](int k0) {
        int r = tid >> 2, c4 = tid & 3;
        aR = *(const float4*)(A + (size_t)(bm + r) * K + k0 + c4 * 4);
    };
    auto loadB = [&](int k0) {
        int kr = tid >> 4, c4 = tid & 15;
        bR = *(const float4*)(Bm + (size_t)(k0 + kr) * N + bn + c4 * 4);
    };
    auto stage = [&](int buf) {
        int r = tid >> 2, c4 = tid & 3;
        As[buf][c4 * 4 + 0][r] = aR.x;
        As[buf][c4 * 4 + 1][r] = aR.y;
        As[buf][c4 * 4 + 2][r] = aR.z;
        As[buf][c4 * 4 + 3][r] = aR.w;
        int kr = tid >> 4, cb = tid & 15;
        *(float4*)&Bs[buf][kr][cb * 4] = bR;
    };
    loadA(0); loadB(0);
    stage(0);
    __syncthreads();
    int buf = 0;
    for (int k0 = 0;;) {
        int kn = k0 + 16;
        if (kn < K) { loadA(kn); loadB(kn); }
        #pragma unroll
        for (int k = 0; k < 16; k++) {
            float4 a = *(const float4*)&As[buf][k][ty * 4];
            ulonglong2 bp = *(const ulonglong2*)&Bs[buf][k][tx * 4];
            float av[4] = {a.x, a.y, a.z, a.w};
            #pragma unroll
            for (int i = 0; i < 4; i++) {
                unsigned long long ad = pk2(av[i]);
                ffma2(acc[i][0], ad, bp.x);
                ffma2(acc[i][1], ad, bp.y);
            }
        }
        if (kn >= K) break;
        stage(buf ^ 1);
        __syncthreads();
        buf ^= 1;
        k0 = kn;
    }
}

__global__ __launch_bounds__(256)
void k_sgemm_bias_s(const float* __restrict__ A, const float* __restrict__ Bm,
                    const float* __restrict__ bias, float* __restrict__ C,
                    int N, int K, int act) {
    unsigned long long acc[4][2] = {};
    int bm = blockIdx.y * 64, bn = blockIdx.x * 64;
    gemm64_2(A, Bm, K, N, bm, bn, acc);
    const int tx = threadIdx.x & 15, ty = threadIdx.x >> 4;
    #pragma unroll
    for (int i = 0; i < 4; i++) {
        int r = bm + ty * 4 + i;
        #pragma unroll
        for (int q = 0; q < 4; q++) {
            int c = bn + tx * 4 + q;
            float v = pick2(acc[i][q >> 1], q & 1) + bias[c];
            if (act) v = v > 0.f ? v : 0.2f * v;
            C[(size_t)r * N + c] = v;
        }
    }
}

__global__ __launch_bounds__(256)
void k_gru_gates_s(const float* __restrict__ Hst, const float* __restrict__ Wgh,
                   const float* __restrict__ Xg, const int* __restrict__ lens,
                   float* __restrict__ RH, float* __restrict__ Ug,
                   int Nseq, int T, int t) {
    unsigned long long acc[4][2] = {};
    int bm = blockIdx.y * 64, bn = blockIdx.x * 64;
    gemm64_2(Hst, Wgh, H, 2 * H, bm, bn, acc);
    const int tx = threadIdx.x & 15, ty = threadIdx.x >> 4;
    bool isR = (bn + 64 <= H);
    #pragma unroll
    for (int i = 0; i < 4; i++) {
        int r = bm + ty * 4 + i;
        int dir = (r >= Nseq);
        int n = dir ? r - Nseq : r;
        int len = lens[n];
        int te = dir ? max(0, min(len - 1 - t, T - 1)) : t;
        const float* xg = Xg + ((size_t)n * T + te) * (2 * H);
        #pragma unroll
        for (int q = 0; q < 4; q++) {
            int c = bn + tx * 4 + q;
            float g = 1.f / (1.f + __expf(-(xg[c] + pick2(acc[i][q >> 1], q & 1))));
            if (isR) RH[(size_t)r * H + c] = g * Hst[(size_t)r * H + c];
            else     Ug[(size_t)r * H + (c - H)] = g;
        }
    }
}

__global__ __launch_bounds__(256)
void k_gru_cand_s(float* __restrict__ Hst, const float* __restrict__ Wch,
                  const float* __restrict__ Xc, const int* __restrict__ lens,
                  const float* __restrict__ RH, const float* __restrict__ Ug,
                  int Nseq, int T, int t) {
    unsigned long long acc[4][2] = {};
    int bm = blockIdx.y * 64, bn = blockIdx.x * 64;
    gemm64_2(RH, Wch, H, H, bm, bn, acc);
    const int tx = threadIdx.x & 15, ty = threadIdx.x >> 4;
    #pragma unroll
    for (int i = 0; i < 4; i++) {
        int r = bm + ty * 4 + i;
        int dir = (r >= Nseq);
        int n = dir ? r - Nseq : r;
        int len = lens[n];
        if (t >= len) continue;
        int te = dir ? max(0, min(len - 1 - t, T - 1)) : t;
        const float* xc = Xc + ((size_t)n * T + te) * H;
        #pragma unroll
        for (int q = 0; q < 4; q++) {
            int c = bn + tx * 4 + q;
            float cc = tanhf(xc[c] + pick2(acc[i][q >> 1], q & 1));
            float h = Hst[(size_t)r * H + c];
            float u = Ug[(size_t)r * H + c];
            Hst[(size_t)r * H + c] = u * h + (1.f - u) * cc;
        }
    }
}

// ---------------- misc small kernels -----------------------------------------
__global__ void k_copy_states(const float* __restrict__ Hw, float* __restrict__ out) {
    int i = blockIdx.x * blockDim.x + threadIdx.x;
    if (i >= B_ * 2 * H) return;
    int c = i % (2 * H);
    int b = i / (2 * H);
    out[i] = (c < H) ? Hw[(size_t)b * H + c] : Hw[(size_t)(B_ + b) * H + (c - H)];
}

__global__ void k_fc2(const float* __restrict__ hidden, const float* __restrict__ W2,
                      const float* __restrict__ b2, float* __restrict__ out) {
    int i = blockIdx.x * blockDim.x + threadIdx.x;
    if (i >= B_ * 2) return;
    int b = i >> 1, j = i & 1;
    float s = b2[j];
    #pragma unroll
    for (int k = 0; k < 64; k++) s = fmaf(hidden[b * 64 + k], W2[k * 2 + j], s);
    out[i] = s;
}

// ---------------- host orchestration ----------------------------------------
extern "C" void kernel_launch(void* const* d_in, const int* in_sizes, int n_in,
                              void* d_out, int out_size) {
    const int*   charseqs      = (const int*)d_in[0];
    const int*   charseq_lens  = (const int*)d_in[1];
    const int*   charseq_ids   = (const int*)d_in[2];
    const int*   word_ids      = (const int*)d_in[3];
    const int*   sentence_lens = (const int*)d_in[4];
    const float* char_emb      = (const float*)d_in[5];
    const float* word_emb      = (const float*)d_in[6];
    const float* Wg_c = (const float*)d_in[7];
    const float* bg_c = (const float*)d_in[8];
    const float* Wc_c = (const float*)d_in[9];
    const float* bc_c = (const float*)d_in[10];
    const float* Wg_w = (const float*)d_in[11];
    const float* bg_w = (const float*)d_in[12];
    const float* Wc_w = (const float*)d_in[13];
    const float* bc_w = (const float*)d_in[14];
    const float* W1   = (const float*)d_in[15];
    const float* b1   = (const float*)d_in[16];
    const float* W2   = (const float*)d_in[17];
    const float* b2   = (const float*)d_in[18];
    float* out = (float*)d_out;

    float *Xg_c, *Xc_c, *Hc, *Uc, *Xg_w, *Xc_w, *Hw, *RHw, *Uw, *states, *hidden;
    __nv_bfloat16 *cAh, *cAl, *wAh, *wAl, *Hch, *Hcl, *RHh, *RHl;
    __nv_bfloat16 *Wgc_h, *Wgc_l, *Wcc_h, *Wcc_l, *Wgw_h, *Wgw_l, *Wcw_h, *Wcw_l;
    __nv_bfloat16 *Wghc_h, *Wghc_l, *Wchc_h, *Wchc_l;
    cudaGetSymbolAddress((void**)&Xg_c,   g_Xg_c);
    cudaGetSymbolAddress((void**)&Xc_c,   g_Xc_c);
    cudaGetSymbolAddress((void**)&Hc,     g_Hc);
    cudaGetSymbolAddress((void**)&Uc,     g_Uc);
    cudaGetSymbolAddress((void**)&Xg_w,   g_Xg_w);
    cudaGetSymbolAddress((void**)&Xc_w,   g_Xc_w);
    cudaGetSymbolAddress((void**)&Hw,     g_Hw);
    cudaGetSymbolAddress((void**)&RHw,    g_RHw);
    cudaGetSymbolAddress((void**)&Uw,     g_Uw);
    cudaGetSymbolAddress((void**)&states, g_states);
    cudaGetSymbolAddress((void**)&hidden, g_hidden);
    cudaGetSymbolAddress((void**)&cAh, g_cAh);
    cudaGetSymbolAddress((void**)&cAl, g_cAl);
    cudaGetSymbolAddress((void**)&wAh, g_wAh);
    cudaGetSymbolAddress((void**)&wAl, g_wAl);
    cudaGetSymbolAddress((void**)&Hch, g_Hch);
    cudaGetSymbolAddress((void**)&Hcl, g_Hcl);
    cudaGetSymbolAddress((void**)&RHh, g_RHh);
    cudaGetSymbolAddress((void**)&RHl, g_RHl);
    cudaGetSymbolAddress((void**)&Wgc_h, g_Wgc_h);
    cudaGetSymbolAddress((void**)&Wgc_l, g_Wgc_l);
    cudaGetSymbolAddress((void**)&Wcc_h, g_Wcc_h);
    cudaGetSymbolAddress((void**)&Wcc_l, g_Wcc_l);
    cudaGetSymbolAddress((void**)&Wgw_h, g_Wgw_h);
    cudaGetSymbolAddress((void**)&Wgw_l, g_Wgw_l);
    cudaGetSymbolAddress((void**)&Wcw_h, g_Wcw_h);
    cudaGetSymbolAddress((void**)&Wcw_l, g_Wcw_l);
    cudaGetSymbolAddress((void**)&Wghc_h, g_Wghc_h);
    cudaGetSymbolAddress((void**)&Wghc_l, g_Wghc_l);
    cudaGetSymbolAddress((void**)&Wchc_h, g_Wchc_h);
    cudaGetSymbolAddress((void**)&Wchc_l, g_Wchc_l);

    // ---- one-time weight splits ----
    k_prep_w<<<(CE * 1024 + 255) / 256, 256>>>(Wg_c, CE, 1024, Wgc_h, Wgc_l);
    k_prep_w<<<(CE * 512 + 255) / 256, 256>>>(Wc_c, CE, 512, Wcc_h, Wcc_l);
    k_prep_w<<<(WD * 1024 + 255) / 256, 256>>>(Wg_w, WD, 1024, Wgw_h, Wgw_l);
    k_prep_w<<<(WD * 512 + 255) / 256, 256>>>(Wc_w, WD, 512, Wcw_h, Wcw_l);
    k_prep_w<<<(H * 1024 + 255) / 256, 256>>>(Wg_c + (size_t)CE * 1024, H, 1024, Wghc_h, Wghc_l);
    k_prep_w<<<(H * 512 + 255) / 256, 256>>>(Wc_c + (size_t)CE * 512, H, 512, Wchc_h, Wchc_l);

    // ---- char bi-GRU over unique word forms ----
    {
        int total = U_ * TC * CE;
        k_gather_char_sp<<<(total + 255) / 256, 256>>>(charseqs, char_emb, cAh, cAl, total);
    }
    k_mm_bias<<<dim3(8, (U_ * TC) / 128), 256>>>(cAh, cAl, Wgc_h, Wgc_l, bg_c, Xg_c, 1024, CE / 32);
    k_mm_bias<<<dim3(4, (U_ * TC) / 128), 256>>>(cAh, cAl, Wcc_h, Wcc_l, bc_c, Xc_c, 512, CE / 32);
    cudaMemsetAsync(Hc, 0, (size_t)2 * U_ * H * sizeof(float));
    cudaMemsetAsync(Hch, 0, (size_t)2 * U_ * H * sizeof(__nv_bfloat16));
    cudaMemsetAsync(Hcl, 0, (size_t)2 * U_ * H * sizeof(__nv_bfloat16));

    for (int t = 0; t < TC; t++) {
        k_gates_mma<<<dim3(8, (2 * U_) / 128), 256>>>(
            Hch, Hcl, Wghc_h, Wghc_l, Xg_c, charseq_lens, Hc, RHh, RHl, Uc, U_, TC, t);
        k_cand_mma<<<dim3(4, (2 * U_) / 128), 256>>>(
            RHh, RHl, Wchc_h, Wchc_l, Xc_c, charseq_lens, Hc, Uc, Hch, Hcl, U_, TC, t);
    }

    // ---- word bi-GRU over sentences ----
    {
        int total = B_ * TW * WD;
        k_gather_word_sp<<<(total + 255) / 256, 256>>>(charseq_ids, word_ids, word_emb, Hc, wAh, wAl);
    }
    k_mm_bias<<<dim3(8, (B_ * TW) / 128), 256>>>(wAh, wAl, Wgw_h, Wgw_l, bg_w, Xg_w, 1024, WD / 32);
    k_mm_bias<<<dim3(4, (B_ * TW) / 128), 256>>>(wAh, wAl, Wcw_h, Wcw_l, bc_w, Xc_w, 512, WD / 32);
    cudaMemsetAsync(Hw, 0, (size_t)2 * B_ * H * sizeof(float));

    // word recurrence: parallelism-limited (M=512) -> scalar FFMA2 path
    const float* Wgh_w = Wg_w + (size_t)WD * 2 * H;
    const float* Wch_w = Wc_w + (size_t)WD * H;
    for (int t = 0; t < TW; t++) {
        k_gru_gates_s<<<dim3((2 * H) / 64, (2 * B_) / 64), 256>>>(
            Hw, Wgh_w, Xg_w, sentence_lens, RHw, Uw, B_, TW, t);
        k_gru_cand_s<<<dim3(H / 64, (2 * B_) / 64), 256>>>(
            Hw, Wch_w, Xc_w, sentence_lens, RHw, Uw, B_, TW, t);
    }

    // ---- head ----
    k_copy_states<<<(B_ * 2 * H + 255) / 256, 256>>>(Hw, states);
    k_sgemm_bias_s<<<dim3(1, B_ / 64), 256>>>(states, W1, b1, hidden, 64, 2 * H, 1);
    k_fc2<<<(B_ * 2 + 255) / 256, 256>>>(hidden, W2, b2, out);
}